// round 17
// baseline (speedup 1.0000x reference)
#include <cuda_runtime.h>
#include <cuda_fp16.h>
#include <math.h>

#define BMAX 4096
#define KP 832           // 784 padded to 13*64
#define LPW 12           // padded logit-partial row width (10 -> 12)

// scratch (no allocations allowed)
__device__ __half g_A[BMAX * KP];            // feats fp16, padded
__device__ __half g_B[256 * KP];             // W1 fp16, padded
__device__ float g_lpart[8 * BMAX * LPW];    // per-slice partial logits

typedef unsigned long long u64;

__device__ __forceinline__ unsigned pack_half2(__half a, __half b) {
    __half2 t = __halves2half2(a, b);
    return *(unsigned*)&t;
}

// ---- packed f32x2 helpers (sm_100+ base ISA) ----
__device__ __forceinline__ u64 pk2(float a, float b) {
    u64 d; asm("mov.b64 %0, {%1, %2};" : "=l"(d) : "f"(a), "f"(b)); return d;
}
__device__ __forceinline__ void upk2(float& a, float& b, u64 d) {
    asm("mov.b64 {%0, %1}, %2;" : "=f"(a), "=f"(b) : "l"(d));
}
__device__ __forceinline__ u64 mul2(u64 a, u64 b) {
    u64 d; asm("mul.rn.f32x2 %0, %1, %2;" : "=l"(d) : "l"(a), "l"(b)); return d;
}
__device__ __forceinline__ u64 add2(u64 a, u64 b) {
    u64 d; asm("add.rn.f32x2 %0, %1, %2;" : "=l"(d) : "l"(a), "l"(b)); return d;
}
__device__ __forceinline__ u64 fma2(u64 a, u64 b, u64 c) {
    u64 d; asm("fma.rn.f32x2 %0, %1, %2, %3;" : "=l"(d) : "l"(a), "l"(b), "l"(c)); return d;
}

// ---------------------------------------------------------------------------
// prep_kernel: blocks [0, qblocks) run quanvolution (2 patches per thread,
// packed f32x2); blocks [qblocks, ...) convert W1 fp32 -> fp16.
// ---------------------------------------------------------------------------
__global__ void prep_kernel(const float* __restrict__ x,
                            const float* __restrict__ var,
                            const float* __restrict__ W1,
                            int B, int qblocks) {
    if ((int)blockIdx.x >= qblocks) {
        // ---- W1 conversion ----
        int t = (blockIdx.x - qblocks) * 256 + threadIdx.x;
        if (t >= 256 * 196) return;
        int n = t / 196;
        int kq = t - n * 196;
        int k = kq * 4;

        float4 w = *(const float4*)(W1 + n * 784 + k);
        uint2 hp;
        hp.x = pack_half2(__float2half_rn(w.x), __float2half_rn(w.y));
        hp.y = pack_half2(__float2half_rn(w.z), __float2half_rn(w.w));

        __half* row = g_B + n * KP;
        *(uint2*)(row + k) = hp;
        if (kq < 12) {
            *(uint2*)(row + 784 + kq * 4) = make_uint2(0u, 0u);  // pad 784..831
        }
        return;
    }

    // ---- quanvolution: thread handles patches p and p+98 of batch row b ----
    __shared__ float sv[12];   // var[0..3], sin(var[4..7]/2), cos(var[4..7]/2)
    if (threadIdx.x < 4) {
        sv[threadIdx.x] = __ldg(var + threadIdx.x);
        float h = 0.5f * __ldg(var + 4 + threadIdx.x);
        sv[4 + threadIdx.x] = __sinf(h);
        sv[8 + threadIdx.x] = __cosf(h);
    }
    __syncthreads();

    int idx = blockIdx.x * blockDim.x + threadIdx.x;
    if (idx >= B * 98) return;
    int b = idx / 98;
    int p = idx - b * 98;       // patch A = p, patch B = p + 98 (rB = r+7)
    int r = p / 14;
    int c = p - r * 14;

    const float* img = x + b * 784;
    float2 topA = *(const float2*)(img + (2 * r) * 28 + 2 * c);
    float2 botA = *(const float2*)(img + (2 * r + 1) * 28 + 2 * c);
    float2 topB = *(const float2*)(img + (2 * r + 14) * 28 + 2 * c);
    float2 botB = *(const float2*)(img + (2 * r + 15) * 28 + 2 * c);

    float angA[4] = {topA.x + sv[0], topA.y + sv[1], botA.x + sv[2], botA.y + sv[3]};
    float angB[4] = {topB.x + sv[0], topB.y + sv[1], botB.x + sv[2], botB.y + sv[3]};

    float ecA[4], esA[4], ecB[4], esB[4];
#pragma unroll
    for (int w = 0; w < 4; ++w) {
        __sincosf(0.5f * angA[w], &esA[w], &ecA[w]);
        __sincosf(0.5f * angB[w], &esB[w], &ecB[w]);
    }

    u64 ec2[4], es2[4];
#pragma unroll
    for (int w = 0; w < 4; ++w) {
        ec2[w] = pk2(ecA[w], ecB[w]);
        es2[w] = pk2(esA[w], esB[w]);
    }

    u64 vs2[4], vc2[4], nvs2[4];
#pragma unroll
    for (int w = 0; w < 4; ++w) {
        float s = sv[4 + w], cc = sv[8 + w];
        vs2[w] = pk2(s, s);
        vc2[w] = pk2(cc, cc);
        nvs2[w] = pk2(-s, -s);
    }

    // product state (packed)
    u64 A01[4], A23[4];
    A01[0] = mul2(ec2[0], ec2[1]); A01[1] = mul2(ec2[0], es2[1]);
    A01[2] = mul2(es2[0], ec2[1]); A01[3] = mul2(es2[0], es2[1]);
    A23[0] = mul2(ec2[2], ec2[3]); A23[1] = mul2(ec2[2], es2[3]);
    A23[2] = mul2(es2[2], ec2[3]); A23[3] = mul2(es2[2], es2[3]);

    u64 st[16];
#pragma unroll
    for (int i = 0; i < 16; ++i) st[i] = mul2(A01[i >> 2], A23[i & 3]);

    // CNOT ring (register permutation, free)
#pragma unroll
    for (int cw = 0; cw < 4; ++cw) {
        int tw = (cw + 1) & 3;
        int cm = 8 >> cw, tm = 8 >> tw;
#pragma unroll
        for (int i = 0; i < 16; ++i) {
            if ((i & cm) && !(i & tm)) {
                int j = i | tm;
                u64 t = st[i]; st[i] = st[j]; st[j] = t;
            }
        }
    }

    // depth-1 RY layer (packed)
#pragma unroll
    for (int w = 0; w < 4; ++w) {
        int mask = 8 >> w;
#pragma unroll
        for (int i = 0; i < 16; ++i) {
            if (!(i & mask)) {
                int j = i | mask;
                u64 a = st[i], bb = st[j];
                st[i] = fma2(vc2[w], a, mul2(nvs2[w], bb));
                st[j] = fma2(vs2[w], a, mul2(vc2[w], bb));
            }
        }
    }

    // CNOT ring (register permutation, free)
#pragma unroll
    for (int cw = 0; cw < 4; ++cw) {
        int tw = (cw + 1) & 3;
        int cm = 8 >> cw, tm = 8 >> tw;
#pragma unroll
        for (int i = 0; i < 16; ++i) {
            if ((i & cm) && !(i & tm)) {
                int j = i | tm;
                u64 t = st[i]; st[i] = st[j]; st[j] = t;
            }
        }
    }

    u64 q[16];
#pragma unroll
    for (int i = 0; i < 16; ++i) q[i] = mul2(st[i], st[i]);

    // shared-subtree sums (packed): f_w = norm - 2*S_w
    u64 t1[8], t2[4];
#pragma unroll
    for (int j = 0; j < 8; ++j) t1[j] = add2(q[2 * j], q[2 * j + 1]);
#pragma unroll
    for (int j = 0; j < 4; ++j) t2[j] = add2(t1[2 * j], t1[2 * j + 1]);
    u64 norm = add2(add2(t2[0], t2[1]), add2(t2[2], t2[3]));
    u64 S0 = add2(t2[2], t2[3]);
    u64 S1 = add2(t2[1], t2[3]);
    u64 S2 = add2(add2(t1[1], t1[3]), add2(t1[5], t1[7]));
    u64 S3 = add2(add2(add2(q[1], q[3]), add2(q[5], q[7])),
                  add2(add2(q[9], q[11]), add2(q[13], q[15])));

    u64 m2 = pk2(-2.f, -2.f);
    u64 fo2[4];
    fo2[0] = fma2(m2, S0, norm);
    fo2[1] = fma2(m2, S1, norm);
    fo2[2] = fma2(m2, S2, norm);
    fo2[3] = fma2(m2, S3, norm);

    float foA[4], foB[4];
#pragma unroll
    for (int w = 0; w < 4; ++w) upk2(foA[w], foB[w], fo2[w]);

    __half* row = g_A + (size_t)b * KP;
    uint2 hpA, hpB;
    hpA.x = pack_half2(__float2half_rn(foA[0]), __float2half_rn(foA[1]));
    hpA.y = pack_half2(__float2half_rn(foA[2]), __float2half_rn(foA[3]));
    hpB.x = pack_half2(__float2half_rn(foB[0]), __float2half_rn(foB[1]));
    hpB.y = pack_half2(__float2half_rn(foB[2]), __float2half_rn(foB[3]));
    *(uint2*)(row + p * 4) = hpA;
    *(uint2*)(row + (p + 98) * 4) = hpB;
    if (p < 12) {
        *(uint2*)(row + 784 + p * 4) = make_uint2(0u, 0u);  // pad 784..831
    }
}

// ---------------------------------------------------------------------------
// Tensor-core GEMM1 + fused logit partials.
// h = relu(A @ B^T + b1); lpart[slice][m][o] = sum_{n in slice} h[m][n]*W2[o][n]
// BM=64, BN=64, BK=64, 4 warps (2x2), warp tile 32x32 via m16n8k16 mma.
// 3-stage cp.async pipeline, one __syncthreads per iter, grid (B/64, 4).
// ---------------------------------------------------------------------------
#define GBK 64
#define NITER (KP / GBK)   // 13
#define ASTRIDE 72         // 144B row stride, ldmatrix conflict-free

__device__ __forceinline__ void mma_f16(float* c, const unsigned* a, const unsigned* b) {
    asm volatile(
        "mma.sync.aligned.m16n8k16.row.col.f32.f16.f16.f32 "
        "{%0,%1,%2,%3}, {%4,%5,%6,%7}, {%8,%9}, {%0,%1,%2,%3};\n"
        : "+f"(c[0]), "+f"(c[1]), "+f"(c[2]), "+f"(c[3])
        : "r"(a[0]), "r"(a[1]), "r"(a[2]), "r"(a[3]), "r"(b[0]), "r"(b[1]));
}

__global__ __launch_bounds__(128, 3) void gemm1_kernel(const float* __restrict__ b1,
                                                       const float* __restrict__ W2) {
    __shared__ __half As[3][64][ASTRIDE];   // 27.6 KB
    __shared__ __half Bs[3][64][ASTRIDE];   // 27.6 KB (total 55.3 KB)

    int tid = threadIdx.x;
    int wid = tid >> 5;
    int lane = tid & 31;
    int warp_m = wid & 1;      // 0..1 -> m offset 32*warp_m
    int warp_n = wid >> 1;     // 0..1 -> n offset 32*warp_n
    int bm = blockIdx.x * 64;
    int bn = blockIdx.y * 64;

    float acc[2][4][4];
#pragma unroll
    for (int i = 0; i < 2; ++i)
#pragma unroll
        for (int j = 0; j < 4; ++j)
#pragma unroll
            for (int k = 0; k < 4; ++k) acc[i][j][k] = 0.f;

#define CPA(dst, src) asm volatile("cp.async.cg.shared.global [%0], [%1], 16;\n" ::"r"(dst), "l"(src))
#define LOAD_STAGE(IT, BUF)                                                      \
    do {                                                                         \
        int k0 = (IT) * GBK;                                                     \
        _Pragma("unroll")                                                        \
        for (int i_ = 0; i_ < 4; ++i_) {                                         \
            int id_ = tid + i_ * 128;                                            \
            int row_ = id_ >> 3, cc_ = id_ & 7;                                  \
            CPA((unsigned)__cvta_generic_to_shared(&As[BUF][row_][cc_ * 8]),     \
                g_A + (size_t)(bm + row_) * KP + k0 + cc_ * 8);                  \
            CPA((unsigned)__cvta_generic_to_shared(&Bs[BUF][row_][cc_ * 8]),     \
                g_B + (size_t)(bn + row_) * KP + k0 + cc_ * 8);                  \
        }                                                                        \
    } while (0)

    LOAD_STAGE(0, 0);
    asm volatile("cp.async.commit_group;\n" ::);
    LOAD_STAGE(1, 1);
    asm volatile("cp.async.commit_group;\n" ::);

    int gid = lane >> 3;   // ldmatrix address group
    int wi = lane & 7;

    for (int it = 0; it < NITER; ++it) {
        int buf = it % 3;
        asm volatile("cp.async.wait_group 1;\n" ::);
        __syncthreads();   // stage `buf` ready; compute of it-1 fully retired

        if (it + 2 < NITER) LOAD_STAGE(it + 2, (it + 2) % 3);
        asm volatile("cp.async.commit_group;\n" ::);

#pragma unroll
        for (int kk = 0; kk < 4; ++kk) {
            unsigned a[2][4];
#pragma unroll
            for (int mf = 0; mf < 2; ++mf) {
                int row = warp_m * 32 + mf * 16 + (gid & 1) * 8 + wi;
                int col = kk * 16 + (gid >> 1) * 8;
                unsigned addr = (unsigned)__cvta_generic_to_shared(&As[buf][row][col]);
                asm volatile(
                    "ldmatrix.sync.aligned.m8n8.x4.shared.b16 {%0,%1,%2,%3}, [%4];\n"
                    : "=r"(a[mf][0]), "=r"(a[mf][1]), "=r"(a[mf][2]), "=r"(a[mf][3])
                    : "r"(addr));
            }
            unsigned b[4][2];
#pragma unroll
            for (int nh = 0; nh < 2; ++nh) {
                int row = warp_n * 32 + nh * 16 + (gid >> 1) * 8 + wi;
                int col = kk * 16 + (gid & 1) * 8;
                unsigned addr = (unsigned)__cvta_generic_to_shared(&Bs[buf][row][col]);
                asm volatile(
                    "ldmatrix.sync.aligned.m8n8.x4.shared.b16 {%0,%1,%2,%3}, [%4];\n"
                    : "=r"(b[2 * nh][0]), "=r"(b[2 * nh][1]),
                      "=r"(b[2 * nh + 1][0]), "=r"(b[2 * nh + 1][1])
                    : "r"(addr));
            }
#pragma unroll
            for (int mf = 0; mf < 2; ++mf)
#pragma unroll
                for (int nf = 0; nf < 4; ++nf) mma_f16(acc[mf][nf], a[mf], b[nf]);
        }
    }

    // ---- fused epilogue: relu(h)+b1 -> partial logits for this 64-col slice
    int nbase = bn + warp_n * 32 + (lane & 3) * 2;
    int slice = blockIdx.y * 2 + warp_n;

    float lp[2][2][10];   // [mf][row-half][output]
#pragma unroll
    for (int mf = 0; mf < 2; ++mf)
#pragma unroll
        for (int rh = 0; rh < 2; ++rh)
#pragma unroll
            for (int o = 0; o < 10; ++o) lp[mf][rh][o] = 0.f;

#pragma unroll
    for (int nf = 0; nf < 4; ++nf) {
        int n = nbase + nf * 8;
        float bx = __ldg(b1 + n), by = __ldg(b1 + n + 1);
        float v[2][2][2];
#pragma unroll
        for (int mf = 0; mf < 2; ++mf) {
            v[mf][0][0] = fmaxf(acc[mf][nf][0] + bx, 0.f);
            v[mf][0][1] = fmaxf(acc[mf][nf][1] + by, 0.f);
            v[mf][1][0] = fmaxf(acc[mf][nf][2] + bx, 0.f);
            v[mf][1][1] = fmaxf(acc[mf][nf][3] + by, 0.f);
        }
#pragma unroll
        for (int o = 0; o < 10; ++o) {
            float w0 = __ldg(W2 + o * 256 + n);
            float w1 = __ldg(W2 + o * 256 + n + 1);
#pragma unroll
            for (int mf = 0; mf < 2; ++mf)
#pragma unroll
                for (int rh = 0; rh < 2; ++rh)
                    lp[mf][rh][o] += v[mf][rh][0] * w0 + v[mf][rh][1] * w1;
        }
    }

    // reduce over the 4 n-lanes (lane&3)
#pragma unroll
    for (int mf = 0; mf < 2; ++mf)
#pragma unroll
        for (int rh = 0; rh < 2; ++rh)
#pragma unroll
            for (int o = 0; o < 10; ++o) {
                lp[mf][rh][o] += __shfl_xor_sync(0xffffffffu, lp[mf][rh][o], 1);
                lp[mf][rh][o] += __shfl_xor_sync(0xffffffffu, lp[mf][rh][o], 2);
            }

    if ((lane & 3) == 0) {
#pragma unroll
        for (int mf = 0; mf < 2; ++mf) {
#pragma unroll
            for (int rh = 0; rh < 2; ++rh) {
                int m = bm + warp_m * 32 + mf * 16 + rh * 8 + (lane >> 2);
                float* dst = g_lpart + ((size_t)slice * BMAX + m) * LPW;
                float4 q0 = make_float4(lp[mf][rh][0], lp[mf][rh][1], lp[mf][rh][2], lp[mf][rh][3]);
                float4 q1 = make_float4(lp[mf][rh][4], lp[mf][rh][5], lp[mf][rh][6], lp[mf][rh][7]);
                float2 q2 = make_float2(lp[mf][rh][8], lp[mf][rh][9]);
                *(float4*)dst = q0;
                *(float4*)(dst + 4) = q1;
                *(float2*)(dst + 8) = q2;
            }
        }
    }
#undef LOAD_STAGE
#undef CPA
}

// ---------------------------------------------------------------------------
// Softmax: 8 lanes per row (one per slice), xor-shuffle reduce, log_softmax.
// Output stores use float2 only: out row stride is 40B (8B-aligned, NOT 16B).
// ---------------------------------------------------------------------------
__global__ __launch_bounds__(256) void softmax_kernel(const float* __restrict__ b2,
                                                      float* __restrict__ out, int B) {
    int t = blockIdx.x * 256 + threadIdx.x;
    int row = t >> 3;
    int s = t & 7;
    if (row >= B) return;

    const float* p = g_lpart + ((size_t)s * BMAX + row) * LPW;
    float4 a = *(const float4*)p;
    float4 b = *(const float4*)(p + 4);
    float2 c = *(const float2*)(p + 8);
    float lg[10] = {a.x, a.y, a.z, a.w, b.x, b.y, b.z, b.w, c.x, c.y};

#pragma unroll
    for (int off = 1; off < 8; off <<= 1)
#pragma unroll
        for (int o = 0; o < 10; ++o)
            lg[o] += __shfl_xor_sync(0xffffffffu, lg[o], off);

    if (s == 0) {
#pragma unroll
        for (int o = 0; o < 10; ++o) lg[o] += __ldg(b2 + o);

        float m = lg[0];
#pragma unroll
        for (int o = 1; o < 10; ++o) m = fmaxf(m, lg[o]);
        float sum = 0.f;
#pragma unroll
        for (int o = 0; o < 10; ++o) sum += expf(lg[o] - m);
        float lse = m + logf(sum);

        float* dst = out + (size_t)row * 10;
#pragma unroll
        for (int o = 0; o < 10; o += 2) {
            float2 q = make_float2(lg[o] - lse, lg[o + 1] - lse);
            *(float2*)(dst + o) = q;   // 8B-aligned for any row
        }
    }
}

// ---------------------------------------------------------------------------
extern "C" void kernel_launch(void* const* d_in, const int* in_sizes, int n_in,
                              void* d_out, int out_size) {
    const float* x   = (const float*)d_in[0];
    const float* var = (const float*)d_in[1];
    const float* W1  = (const float*)d_in[2];
    const float* b1  = (const float*)d_in[3];
    const float* W2  = (const float*)d_in[4];
    const float* b2  = (const float*)d_in[5];
    float* out = (float*)d_out;

    int B = in_sizes[0] / 784;

    int qblocks = (B * 98 + 255) / 256;           // quanv blocks (2 patches/thread)
    int cblocks = (256 * 196 + 255) / 256;        // W1-convert blocks
    prep_kernel<<<qblocks + cblocks, 256>>>(x, var, W1, B, qblocks);

    dim3 g1(B / 64, 4);
    gemm1_kernel<<<g1, 128>>>(b1, W2);

    softmax_kernel<<<(B * 8 + 255) / 256, 256>>>(b2, out, B);
}